// round 5
// baseline (speedup 1.0000x reference)
#include <cuda_runtime.h>
#include <cuda_bf16.h>
#include <cstdint>

#define IMG_N 128
#define B_N 64
#define PIX 262144
#define CAP 4096
#define NSAMP 1000
// valid ord = 0x800000 + k, k in [0, 2^22]. Threshold => E[candidates] ~ 3050.
#define K0_ORD 0xBF4000u
#define SENT 1.0e6f

// ---------------- static scratch (no allocations allowed) ----------------
__device__ uint2 g_imgkeys[IMG_N];
__device__ unsigned char g_valid[(size_t)IMG_N * PIX];      // 33.5 MB (fallback only)
__device__ unsigned long long g_cand[IMG_N * CAP];          // 4 MB
__device__ unsigned int g_candCnt[IMG_N];
__device__ unsigned int g_validCnt[IMG_N];
__device__ float2 g_pts[IMG_N * NSAMP];
__device__ float g_pval[IMG_N * NSAMP];
__device__ float g_a2[B_N * 2];

// ---------------- threefry2x32 core ----------------
__device__ __forceinline__ uint2 threefry(unsigned k0, unsigned k1,
                                          unsigned x0, unsigned x1) {
    unsigned ks2 = k0 ^ k1 ^ 0x1BD11BDAu;
    x0 += k0; x1 += k1;
#define TF_RND(r) { x0 += x1; x1 = __funnelshift_l(x1, x1, (r)); x1 ^= x0; }
    TF_RND(13) TF_RND(15) TF_RND(26) TF_RND(6)   x0 += k1;  x1 += ks2 + 1u;
    TF_RND(17) TF_RND(29) TF_RND(16) TF_RND(24)  x0 += ks2; x1 += k0 + 2u;
    TF_RND(13) TF_RND(15) TF_RND(26) TF_RND(6)   x0 += k0;  x1 += k1 + 3u;
    TF_RND(17) TF_RND(29) TF_RND(16) TF_RND(24)  x0 += k1;  x1 += ks2 + 4u;
    TF_RND(13) TF_RND(15) TF_RND(26) TF_RND(6)   x0 += ks2; x1 += k0 + 5u;
#undef TF_RND
    return make_uint2(x0, x1);
}

// partitionable random_bits(32): one threefry per element, counter=(0, j), out = v0 ^ v1
__device__ __forceinline__ unsigned tfBits32(unsigned k0, unsigned k1, unsigned j) {
    uint2 r = threefry(k0, k1, 0u, j);
    return r.x ^ r.y;
}

// Order key for a VALID pixel: monotone in score = RNE(2.0f + u), u = (bits>>9)*2^-23.
__device__ __forceinline__ unsigned makeOrdValid(unsigned bits) {
    unsigned m = bits >> 9;
    float u = __uint_as_float(0x3F800000u | m) - 1.0f;  // exact
    float s = 2.0f + u;                                  // hardware RNE == XLA add
    return 0x800000u + (__float_as_uint(s) - 0x40000000u);
}

// ---------------- kernels ----------------
__global__ void kernZero() {
    int t = threadIdx.x;
    if (t < IMG_N) { g_candCnt[t] = 0u; g_validCnt[t] = 0u; }
}

// foldlike split: keys = split(key(1), 128): key_j = threefry(0,1, hi=0, lo=j)
__global__ void kernImgKeys() {
    unsigned j = threadIdx.x;
    if (j >= IMG_N) return;
    g_imgkeys[j] = threefry(0u, 1u, 0u, j);
}

// FUSED: sigmoid/identity -> Sobel -> valid -> threefry -> candidate collection.
// Writes g_valid only for the (never-triggering) fallback path.
__global__ __launch_bounds__(1024) void kernValidCand(const float* __restrict__ pred,
                                                      const float* __restrict__ tgt) {
    __shared__ float s[34][36];
    __shared__ unsigned wcnt[32];
    int img = blockIdx.z;
    int bx = blockIdx.x * 32, by = blockIdx.y * 32;
    int tx = threadIdx.x, ty = threadIdx.y;
    int tid = ty * 32 + tx;
    const float* src = (img < 64) ? (pred + (size_t)img * PIX)
                                  : (tgt + (size_t)(img - 64) * PIX);
    bool isPred = img < 64;
    for (int i = tid; i < 34 * 34; i += 1024) {
        int hy = i / 34, hx = i % 34;
        int gy = by + hy - 1, gx = bx + hx - 1;
        float v = 0.0f;
        if (gy >= 0 && gy < 512 && gx >= 0 && gx < 512) {
            v = __ldg(src + (size_t)gy * 512 + gx);
            if (isPred) v = 1.0f / (1.0f + expf(-v));
        }
        s[hy][hx] = v;
    }
    __syncthreads();
    int hy = ty + 1, hx = tx + 1;
    float a00 = s[hy - 1][hx - 1], a01 = s[hy - 1][hx], a02 = s[hy - 1][hx + 1];
    float a10 = s[hy][hx - 1],                          a12 = s[hy][hx + 1];
    float a20 = s[hy + 1][hx - 1], a21 = s[hy + 1][hx], a22 = s[hy + 1][hx + 1];
    float gxv = (a02 - a00) + 2.0f * (a12 - a10) + (a22 - a20);
    float gyv = (a20 - a00) + 2.0f * (a21 - a01) + (a22 - a02);
    float v2 = gxv * gxv + gyv * gyv + 1e-8f;
    int valid = (__fsqrt_rn(v2) > 0.1f) ? 1 : 0;
    unsigned j = (unsigned)(by + ty) * 512u + (unsigned)(bx + tx);
    g_valid[(size_t)img * PIX + j] = (unsigned char)valid;

    // per-image valid count (for fallback decision)
    unsigned bal = __ballot_sync(0xFFFFFFFFu, valid);
    if ((tid & 31) == 0) wcnt[tid >> 5] = __popc(bal);

    // threefry + candidate collection, straight from the in-register valid flag
    uint2 kk = g_imgkeys[img];
    unsigned ord = 0;
    bool c = false;
    if (valid) {
        ord = makeOrdValid(tfBits32(kk.x, kk.y, j));
        c = (ord >= K0_ORD);
    }
    unsigned lane = (unsigned)tid & 31u;
    unsigned lmask = (1u << lane) - 1u;
    unsigned m = __ballot_sync(0xFFFFFFFFu, c);
    if (m) {
        unsigned base = 0;
        int leader = __ffs(m) - 1;
        if ((int)lane == leader) base = atomicAdd(&g_candCnt[img], (unsigned)__popc(m));
        base = __shfl_sync(0xFFFFFFFFu, base, leader);
        if (c) {
            unsigned pos = base + __popc(m & lmask);
            if (pos < CAP)
                g_cand[(size_t)img * CAP + pos] =
                    ((unsigned long long)ord << 18) | (unsigned long long)(j ^ 0x3FFFFu);
        }
    }
    __syncthreads();
    if (tid == 0) {
        unsigned sum = 0;
        for (int w = 0; w < 32; w++) sum += wcnt[w];
        atomicAdd(&g_validCnt[img], sum);
    }
}

// per-image bitonic sort of <=4096 candidates (descending), emit top 1000 points
__global__ __launch_bounds__(1024) void kernSort() {
    __shared__ unsigned long long s[CAP];
    int img = blockIdx.x;
    unsigned cnt = g_candCnt[img];
    unsigned n = cnt > CAP ? CAP : cnt;
    for (int i = threadIdx.x; i < CAP; i += 1024)
        s[i] = (i < (int)n) ? g_cand[(size_t)img * CAP + i] : 0ull;
    __syncthreads();
    for (int k = 2; k <= CAP; k <<= 1) {
        for (int jj = k >> 1; jj > 0; jj >>= 1) {
            for (int i = threadIdx.x; i < CAP; i += 1024) {
                int ixj = i ^ jj;
                if (ixj > i) {
                    unsigned long long a = s[i], b = s[ixj];
                    bool desc = (i & k) == 0;
                    if (desc ? (a < b) : (a > b)) { s[i] = b; s[ixj] = a; }
                }
            }
            __syncthreads();
        }
    }
    if (threadIdx.x < NSAMP) {
        unsigned long long p = s[threadIdx.x];
        unsigned idx = ((unsigned)p & 0x3FFFFu) ^ 0x3FFFFu;
        g_pts[img * NSAMP + threadIdx.x] =
            make_float2((float)(idx >> 9), (float)(idx & 511u));
        g_pval[img * NSAMP + threadIdx.x] = 1.0f;
    }
}

// exact fallback for degenerate images (never triggers on healthy inputs)
__global__ __launch_bounds__(256) void kernFallback() {
    int img = blockIdx.x;
    unsigned V = g_validCnt[img];
    unsigned cnt = g_candCnt[img];
    bool need = (V < NSAMP) || (cnt < NSAMP) || (cnt > CAP);
    if (!need) return;
    int tid = threadIdx.x;
    size_t base = (size_t)img * PIX;
    float2* pts = g_pts + img * NSAMP;
    float* pv = g_pval + img * NSAMP;

    if (V == 0) {  // has_any == False: single center point
        for (int i = tid; i < NSAMP; i += 256) {
            pts[i] = (i == 0) ? make_float2(256.0f, 256.0f) : make_float2(SENT, SENT);
            pv[i] = (i == 0) ? 1.0f : 0.0f;
        }
        return;
    }
    if (V < NSAMP) {  // take ALL valid points; rest masked
        __shared__ unsigned c2;
        if (tid == 0) c2 = 0;
        __syncthreads();
        for (unsigned p = tid; p < PIX; p += 256) {
            if (g_valid[base + p]) {
                unsigned pos = atomicAdd(&c2, 1u);
                pts[pos] = make_float2((float)(p >> 9), (float)(p & 511u));
                pv[pos] = 1.0f;
            }
        }
        __syncthreads();
        for (unsigned i = V + tid; i < NSAMP; i += 256) {
            pts[i] = make_float2(SENT, SENT);
            pv[i] = 0.0f;
        }
        return;
    }
    // V >= NSAMP but threshold capture failed: exact radix select over valid ords
    __shared__ unsigned hist[2048];
    __shared__ unsigned long long buf[2048];
    __shared__ unsigned bufCnt, outCnt, selB, selNeed;
    for (int i = tid; i < 2048; i += 256) hist[i] = 0;
    if (tid == 0) { bufCnt = 0; outCnt = 0; }
    __syncthreads();
    uint2 kk = g_imgkeys[img];
    for (unsigned j = tid; j < PIX; j += 256) {
        if (g_valid[base + j]) {
            unsigned k = makeOrdValid(tfBits32(kk.x, kk.y, j)) - 0x800000u;
            atomicAdd(&hist[min(k >> 11, 2047u)], 1u);
        }
    }
    __syncthreads();
    if (tid == 0) {
        unsigned acc = 0; int b = 2047;
        for (; b > 0; b--) {
            if (acc + hist[b] >= NSAMP) break;
            acc += hist[b];
        }
        selB = (unsigned)b;
        selNeed = NSAMP - acc;
    }
    __syncthreads();
    unsigned sb = selB;
    for (unsigned j = tid; j < PIX; j += 256) {
        if (!g_valid[base + j]) continue;
        unsigned k = makeOrdValid(tfBits32(kk.x, kk.y, j)) - 0x800000u;
        unsigned bk = min(k >> 11, 2047u);
        if (bk > sb) {
            unsigned pos = atomicAdd(&outCnt, 1u);
            pts[pos] = make_float2((float)(j >> 9), (float)(j & 511u));
            pv[pos] = 1.0f;
        } else if (bk == sb) {
            unsigned pos = atomicAdd(&bufCnt, 1u);
            if (pos < 2048u)
                buf[pos] = ((unsigned long long)k << 18) |
                           (unsigned long long)(j ^ 0x3FFFFu);
        }
    }
    __syncthreads();
    unsigned bn = min(bufCnt, 2048u);
    for (int i = tid; i < 2048; i += 256)
        if (i >= (int)bn) buf[i] = 0ull;
    __syncthreads();
    for (int k2 = 2; k2 <= 2048; k2 <<= 1) {
        for (int jj = k2 >> 1; jj > 0; jj >>= 1) {
            for (int i = tid; i < 2048; i += 256) {
                int ixj = i ^ jj;
                if (ixj > i) {
                    unsigned long long a = buf[i], b = buf[ixj];
                    if (((i & k2) == 0) ? (a < b) : (a > b)) { buf[i] = b; buf[ixj] = a; }
                }
            }
            __syncthreads();
        }
    }
    unsigned baseOut = outCnt;
    for (unsigned i = tid; i < selNeed; i += 256) {
        unsigned long long p = buf[i];
        unsigned idx = ((unsigned)p & 0x3FFFFu) ^ 0x3FFFFu;
        pts[baseOut + i] = make_float2((float)(idx >> 9), (float)(idx & 511u));
        pv[baseOut + i] = 1.0f;
    }
}

// directed Hausdorff in d^2 space: block (b, dir) computes max over valid p of
// min over valid t of d2 (masked t points sit at sentinel coords -> never min).
// 4 independent min accumulators break the fmin latency chain (min is exactly
// associative, so the result is bit-identical).
__global__ __launch_bounds__(1024) void kernHaus() {
    __shared__ float2 tp[NSAMP];
    __shared__ float wmax[32];
    int b = blockIdx.x;
    int dir = blockIdx.y;
    int pimg = dir == 0 ? b : 64 + b;
    int timg = dir == 0 ? 64 + b : b;
    int tid = threadIdx.x;
    for (int i = tid; i < NSAMP; i += 1024) tp[i] = g_pts[timg * NSAMP + i];
    __syncthreads();
    float best = -1.0f;
    if (tid < NSAMP) {
        float2 p = g_pts[pimg * NSAMP + tid];
        float pvv = g_pval[pimg * NSAMP + tid];
        float m0 = 3.4e38f, m1 = 3.4e38f, m2 = 3.4e38f, m3 = 3.4e38f;
        int t = 0;
#pragma unroll 2
        for (; t + 4 <= NSAMP; t += 4) {
            float dx0 = p.x - tp[t].x,     dy0 = p.y - tp[t].y;
            float dx1 = p.x - tp[t + 1].x, dy1 = p.y - tp[t + 1].y;
            float dx2 = p.x - tp[t + 2].x, dy2 = p.y - tp[t + 2].y;
            float dx3 = p.x - tp[t + 3].x, dy3 = p.y - tp[t + 3].y;
            m0 = fminf(m0, fmaf(dx0, dx0, dy0 * dy0));
            m1 = fminf(m1, fmaf(dx1, dx1, dy1 * dy1));
            m2 = fminf(m2, fmaf(dx2, dx2, dy2 * dy2));
            m3 = fminf(m3, fmaf(dx3, dx3, dy3 * dy3));
        }
        for (; t < NSAMP; t++) {
            float dx = p.x - tp[t].x, dy = p.y - tp[t].y;
            m0 = fminf(m0, fmaf(dx, dx, dy * dy));
        }
        float mm = fminf(fminf(m0, m1), fminf(m2, m3));
        best = (pvv > 0.0f) ? mm : -1.0f;
    }
    for (int o = 16; o > 0; o >>= 1)
        best = fmaxf(best, __shfl_xor_sync(0xFFFFFFFFu, best, o));
    if ((tid & 31) == 0) wmax[tid >> 5] = best;
    __syncthreads();
    if (tid == 0) {
        float r = wmax[0];
        for (int w = 1; w < 32; w++) r = fmaxf(r, wmax[w]);
        g_a2[b * 2 + dir] = r;
    }
}

__global__ void kernFinal(float* __restrict__ out) {
    __shared__ float hd[64];
    int t = threadIdx.x;
    if (t < 64) {
        float a = __fsqrt_rn(g_a2[t * 2 + 0]);
        float c = __fsqrt_rn(g_a2[t * 2 + 1]);
        float m = fmaxf(a, c);
        float diag = __fsqrt_rn(524288.0f);
        float h = __fdiv_rn(m, diag);
        h = fminf(fmaxf(h, 0.0f), 0.1f);
        hd[t] = h;
    }
    __syncthreads();
    if (t == 0) {
        float s = 0.0f;
        for (int i = 0; i < 64; i++) s += hd[i];
        out[0] = s * (1.0f / 64.0f);
    }
}

extern "C" void kernel_launch(void* const* d_in, const int* in_sizes, int n_in,
                              void* d_out, int out_size) {
    const float* pred = (const float*)d_in[0];
    const float* tgt = (const float*)d_in[1];
    float* out = (float*)d_out;
    kernZero<<<1, 128>>>();
    kernImgKeys<<<1, 128>>>();
    kernValidCand<<<dim3(16, 16, 128), dim3(32, 32)>>>(pred, tgt);
    kernSort<<<128, 1024>>>();
    kernFallback<<<128, 256>>>();
    kernHaus<<<dim3(64, 2), 1024>>>();
    kernFinal<<<1, 64>>>(out);
}